// round 3
// baseline (speedup 1.0000x reference)
#include <cuda_runtime.h>

// ---------------------------------------------------------------------------
// GraphRNNDecoder rollout. N=4096 rows, T=128 steps, D=4, H=256.
// 128 persistent CTAs x 1024 threads, 32 rows per CTA.
// R3: 4-gate register blocking (LDS wf /4), fused LSTM elementwise (no gates
// array, 4 barriers/step), blocked fc1/fc2 on 256 threads, parallel fc3.
// ---------------------------------------------------------------------------

#define T_STEPS 128
#define DIN     4
#define HID     256
#define G4      1024
#define MROWS   32
#define NCTA    128
#define KC      64

// k-chunk packed weights [kc][j] -> float4 of W[j][4kc..4kc+3]; one pad row.
__device__ float4 g_whh[(KC + 1) * G4];
__device__ float4 g_fc1[(KC + 1) * HID];
__device__ float4 g_fc2[(KC + 1) * HID];

__global__ void pack_kernel(const float* __restrict__ W_hh,
                            const float* __restrict__ fc1_w,
                            const float* __restrict__ fc2_w) {
    int i = blockIdx.x * blockDim.x + threadIdx.x;
    if (i < KC * G4) {
        int kc = i >> 10, j = i & 1023;
        g_whh[i] = *reinterpret_cast<const float4*>(W_hh + j * HID + kc * 4);
    }
    if (i < KC * HID) {
        int kc = i >> 8, j = i & 255;
        g_fc1[i] = *reinterpret_cast<const float4*>(fc1_w + j * HID + kc * 4);
        g_fc2[i] = *reinterpret_cast<const float4*>(fc2_w + j * HID + kc * 4);
    }
}

// ---- packed f32x2 helpers --------------------------------------------------
__device__ __forceinline__ unsigned long long pk2(float lo, float hi) {
    unsigned long long r;
    asm("mov.b64 %0, {%1, %2};" : "=l"(r) : "f"(lo), "f"(hi));
    return r;
}
__device__ __forceinline__ void fma2(unsigned long long& d,
                                     unsigned long long a,
                                     unsigned long long b) {
    asm("fma.rn.f32x2 %0, %1, %2, %0;" : "+l"(d) : "l"(a), "l"(b));
}
__device__ __forceinline__ void unpk2(unsigned long long v, float& lo, float& hi) {
    asm("mov.b64 {%0, %1}, %2;" : "=f"(lo), "=f"(hi) : "l"(v));
}
__device__ __forceinline__ float sigf(float x) {
    return __fdividef(1.0f, 1.0f + __expf(-x));
}
__device__ __forceinline__ float tanhf_fast(float x) {
    float e = __expf(2.0f * x);
    return 1.0f - __fdividef(2.0f, e + 1.0f);
}

// ---- shared layout (float offsets) -----------------------------------------
// 3 rotating [256][36] buffers (h_in / h_out=p1 / p2), c state, prev, consts.
#define SBUF      9216          // 256*36
#define OFF_BUF0  0
#define OFF_C     27648         // [256][33] = 8448
#define OFF_PREV  36096         // [32][4]   = 128
#define OFF_WIH   36224         // [1024][4] = 4096
#define OFF_BG    40320         // [1024]
#define OFF_FB1   41344         // [256]
#define OFF_FB2   41600         // [256]
#define OFF_FC3   41856         // fc3T [256][4] = 1024 (k-major transpose)
#define OFF_B3    42880         // [4]
#define SMEM_FLOATS 42884
#define SMEM_BYTES  (SMEM_FLOATS * 4)

// fc block: 4 outputs (i*64+jg) x 8 rows (m0..m0+7), relu, dst [k][36]-layout
__device__ __forceinline__ void fc_block(const float* __restrict__ src,
                                         float* __restrict__ dst,
                                         const float4* __restrict__ wbase,
                                         const float* __restrict__ bsh,
                                         int jg, int m0) {
    unsigned long long acc[4][4];
#pragma unroll
    for (int i = 0; i < 4; i++) {
        float b = bsh[i * 64 + jg];
        unsigned long long bb = pk2(b, b);
        acc[i][0] = bb; acc[i][1] = bb; acc[i][2] = bb; acc[i][3] = bb;
    }
    const float4* wp4 = wbase + jg;
#pragma unroll 1
    for (int kc = 0; kc < KC; kc++) {
        float wa[4][4];
        *(float4*)wa[0] = wp4[kc * HID];
        *(float4*)wa[1] = wp4[kc * HID + 64];
        *(float4*)wa[2] = wp4[kc * HID + 128];
        *(float4*)wa[3] = wp4[kc * HID + 192];
        const float* hb = src + kc * 144 + m0;
#pragma unroll
        for (int kk = 0; kk < 4; kk++) {
            ulonglong2 hA = *reinterpret_cast<const ulonglong2*>(hb + kk * 36);
            ulonglong2 hB = *reinterpret_cast<const ulonglong2*>(hb + kk * 36 + 4);
#pragma unroll
            for (int i = 0; i < 4; i++) {
                unsigned long long w = pk2(wa[i][kk], wa[i][kk]);
                fma2(acc[i][0], w, hA.x);
                fma2(acc[i][1], w, hA.y);
                fma2(acc[i][2], w, hB.x);
                fma2(acc[i][3], w, hB.y);
            }
        }
    }
#pragma unroll
    for (int i = 0; i < 4; i++) {
        int j = i * 64 + jg;
        float r[8];
#pragma unroll
        for (int p = 0; p < 4; p++) {
            float lo, hi; unpk2(acc[i][p], lo, hi);
            r[2 * p]     = fmaxf(lo, 0.0f);
            r[2 * p + 1] = fmaxf(hi, 0.0f);
        }
        float4* dp = reinterpret_cast<float4*>(dst + j * 36 + m0);
        dp[0] = make_float4(r[0], r[1], r[2], r[3]);
        dp[1] = make_float4(r[4], r[5], r[6], r[7]);
    }
}

__global__ void __launch_bounds__(1024, 1)
rnn_rollout_kernel(const float* __restrict__ inputs,
                   const float* __restrict__ W_ih,
                   const float* __restrict__ b_ih,
                   const float* __restrict__ b_hh,
                   const float* __restrict__ fc1_b,
                   const float* __restrict__ fc2_b,
                   const float* __restrict__ fc3_w,
                   const float* __restrict__ fc3_b,
                   float* __restrict__ out) {
    extern __shared__ float sm[];
    float* buf    = sm + OFF_BUF0;   // 3 x [256][36]
    float* csh    = sm + OFF_C;      // [256][33]
    float* prevsh = sm + OFF_PREV;   // [32][4]
    float* wihsh  = sm + OFF_WIH;    // [1024][4]
    float* bgsh   = sm + OFF_BG;     // [1024]
    float* fb1sh  = sm + OFF_FB1;    // [256]
    float* fb2sh  = sm + OFF_FB2;    // [256]
    float* fc3T   = sm + OFF_FC3;    // [256][4]  fc3T[k*4+d] = fc3_w[d*256+k]
    float* b3sh   = sm + OFF_B3;     // [4]

    const int tid  = threadIdx.x;
    const int j2   = tid & 255;      // hidden / gate unit
    const int q    = tid >> 8;       // row quarter 0..3
    const int n0   = q * 8;
    const int row0 = blockIdx.x * MROWS;

    // ---- one-time init ----
    for (int i = tid; i < G4; i += 1024) {
        *reinterpret_cast<float4*>(wihsh + 4 * i) =
            *reinterpret_cast<const float4*>(W_ih + 4 * i);
        bgsh[i] = b_ih[i] + b_hh[i];
    }
    if (tid < HID) { fb1sh[tid] = fc1_b[tid]; fb2sh[tid] = fc2_b[tid]; }
    if (tid < G4)  fc3T[tid] = fc3_w[(tid & 3) * HID + (tid >> 2)];
    if (tid < DIN) b3sh[tid] = fc3_b[tid];
    for (int i = tid; i < SBUF; i += 1024) buf[i] = 0.0f;        // h0 = 0
    for (int i = tid; i < 8448; i += 1024) csh[i] = 0.0f;        // c0 = 0
    if (tid < MROWS * DIN)
        prevsh[tid] = inputs[((size_t)(row0 + (tid >> 2)) * T_STEPS) * DIN + (tid & 3)];
    __syncthreads();

    for (int t = 0; t < T_STEPS; t++) {
        float* hin  = buf + (t & 1) * SBUF;
        float* hout = buf + ((t & 1) ^ 1) * SBUF;
        float* p1   = hin;                 // fc1 overwrites dead h_in
        float* p2   = buf + 2 * SBUF;

        // ---- phase A: gate GEMM, thread = (unit j2, 4 gates, rows n0..n0+7)
        unsigned long long acc[4][4];
        {
            float4 wg0 = *reinterpret_cast<const float4*>(wihsh + 4 * j2);
            float4 wg1 = *reinterpret_cast<const float4*>(wihsh + 4 * (256 + j2));
            float4 wg2 = *reinterpret_cast<const float4*>(wihsh + 4 * (512 + j2));
            float4 wg3 = *reinterpret_cast<const float4*>(wihsh + 4 * (768 + j2));
            float b0 = bgsh[j2], b1 = bgsh[256 + j2];
            float b2 = bgsh[512 + j2], b3 = bgsh[768 + j2];
#pragma unroll
            for (int p = 0; p < 4; p++) {
                float4 pa = *reinterpret_cast<const float4*>(prevsh + 4 * (n0 + 2 * p));
                float4 pb = *reinterpret_cast<const float4*>(prevsh + 4 * (n0 + 2 * p + 1));
                acc[0][p] = pk2(b0 + wg0.x*pa.x + wg0.y*pa.y + wg0.z*pa.z + wg0.w*pa.w,
                                b0 + wg0.x*pb.x + wg0.y*pb.y + wg0.z*pb.z + wg0.w*pb.w);
                acc[1][p] = pk2(b1 + wg1.x*pa.x + wg1.y*pa.y + wg1.z*pa.z + wg1.w*pa.w,
                                b1 + wg1.x*pb.x + wg1.y*pb.y + wg1.z*pb.z + wg1.w*pb.w);
                acc[2][p] = pk2(b2 + wg2.x*pa.x + wg2.y*pa.y + wg2.z*pa.z + wg2.w*pa.w,
                                b2 + wg2.x*pb.x + wg2.y*pb.y + wg2.z*pb.z + wg2.w*pb.w);
                acc[3][p] = pk2(b3 + wg3.x*pa.x + wg3.y*pa.y + wg3.z*pa.z + wg3.w*pa.w,
                                b3 + wg3.x*pb.x + wg3.y*pb.y + wg3.z*pb.z + wg3.w*pb.w);
            }
        }
        const float4* gw = g_whh + j2;
#pragma unroll 1
        for (int kc = 0; kc < KC; kc++) {
            float wa[4][4];
            *(float4*)wa[0] = gw[kc * G4];
            *(float4*)wa[1] = gw[kc * G4 + 256];
            *(float4*)wa[2] = gw[kc * G4 + 512];
            *(float4*)wa[3] = gw[kc * G4 + 768];
            const float* hb = hin + kc * 144 + n0;
#pragma unroll
            for (int kk = 0; kk < 4; kk++) {
                ulonglong2 hA = *reinterpret_cast<const ulonglong2*>(hb + kk * 36);
                ulonglong2 hB = *reinterpret_cast<const ulonglong2*>(hb + kk * 36 + 4);
#pragma unroll
                for (int g = 0; g < 4; g++) {
                    unsigned long long w = pk2(wa[g][kk], wa[g][kk]);
                    fma2(acc[g][0], w, hA.x);
                    fma2(acc[g][1], w, hA.y);
                    fma2(acc[g][2], w, hB.x);
                    fma2(acc[g][3], w, hB.y);
                }
            }
        }

        // ---- phase B (fused): LSTM elementwise, c in smem, h -> hout
#pragma unroll
        for (int p = 0; p < 4; p++) {
            float gi0, gi1, gf0, gf1, gg0, gg1, go0, go1;
            unpk2(acc[0][p], gi0, gi1);
            unpk2(acc[1][p], gf0, gf1);
            unpk2(acc[2][p], gg0, gg1);
            unpk2(acc[3][p], go0, go1);
            const int n = n0 + 2 * p;
            float c0 = sigf(gf0) * csh[j2 * 33 + n]     + sigf(gi0) * tanhf_fast(gg0);
            float c1 = sigf(gf1) * csh[j2 * 33 + n + 1] + sigf(gi1) * tanhf_fast(gg1);
            csh[j2 * 33 + n]     = c0;
            csh[j2 * 33 + n + 1] = c1;
            hout[j2 * 36 + n]     = sigf(go0) * tanhf_fast(c0);
            hout[j2 * 36 + n + 1] = sigf(go1) * tanhf_fast(c1);
        }
        __syncthreads();

        // ---- phase C: fc1 (hout -> p1), 256 threads, 4 outputs x 8 rows each
        if (tid < 256)
            fc_block(hout, p1, g_fc1, fb1sh, tid & 63, (tid >> 6) * 8);
        __syncthreads();

        // ---- phase D: fc2 (p1 -> p2)
        if (tid < 256)
            fc_block(p1, p2, g_fc2, fb2sh, tid & 63, (tid >> 6) * 8);
        __syncthreads();

        // ---- phase E: fc3 + residual, 512 threads: (row n, dim d, k-slice s)
        if (tid < 512) {
            const int n = tid >> 4, d = (tid >> 2) & 3, s = tid & 3;
            const float* pp = p2 + n;
            float a0 = 0.0f, a1 = 0.0f, a2 = 0.0f, a3 = 0.0f;
#pragma unroll
            for (int i = 0; i < 64; i += 4) {
                int k0 = (i + 0) * 4 + s, k1 = (i + 1) * 4 + s;
                int k2 = (i + 2) * 4 + s, k3 = (i + 3) * 4 + s;
                a0 = fmaf(pp[k0 * 36], fc3T[k0 * 4 + d], a0);
                a1 = fmaf(pp[k1 * 36], fc3T[k1 * 4 + d], a1);
                a2 = fmaf(pp[k2 * 36], fc3T[k2 * 4 + d], a2);
                a3 = fmaf(pp[k3 * 36], fc3T[k3 * 4 + d], a3);
            }
            float a = (a0 + a1) + (a2 + a3);
            a += __shfl_xor_sync(0xffffffffu, a, 1);
            a += __shfl_xor_sync(0xffffffffu, a, 2);
            if (s == 0) {
                float r = a + b3sh[d] + prevsh[n * 4 + d];
                out[((size_t)(row0 + n) * T_STEPS + t) * DIN + d] = r;
                prevsh[n * 4 + d] = r;
            }
        }
        __syncthreads();
    }
}

extern "C" void kernel_launch(void* const* d_in, const int* in_sizes, int n_in,
                              void* d_out, int out_size) {
    const float* inputs = (const float*)d_in[0];
    const float* W_ih   = (const float*)d_in[1];
    const float* W_hh   = (const float*)d_in[2];
    const float* b_ih   = (const float*)d_in[3];
    const float* b_hh   = (const float*)d_in[4];
    const float* fc1_w  = (const float*)d_in[5];
    const float* fc1_b  = (const float*)d_in[6];
    const float* fc2_w  = (const float*)d_in[7];
    const float* fc2_b  = (const float*)d_in[8];
    const float* fc3_w  = (const float*)d_in[9];
    const float* fc3_b  = (const float*)d_in[10];
    float* out = (float*)d_out;

    pack_kernel<<<64, 1024>>>(W_hh, fc1_w, fc2_w);

    cudaFuncSetAttribute(rnn_rollout_kernel,
                         cudaFuncAttributeMaxDynamicSharedMemorySize, SMEM_BYTES);
    rnn_rollout_kernel<<<NCTA, 1024, SMEM_BYTES>>>(
        inputs, W_ih, b_ih, b_hh, fc1_b, fc2_b, fc3_w, fc3_b, out);
}

// round 4
// speedup vs baseline: 1.1213x; 1.1213x over previous
#include <cuda_runtime.h>

// ---------------------------------------------------------------------------
// GraphRNNDecoder rollout. N=4096 rows, T=128 steps, D=4, H=256.
// 128 persistent CTAs x 1024 threads, 32 rows per CTA.
// R4: the step decomposes into 4 independent 8-row groups (quarters).
// Quarter q = warps 8q..8q+7 runs the whole step pipeline on its rows with
// ONLY 256-thread named barriers (bar.sync q+1,256) -> 4 free-running streams
// per CTA, no full-CTA sync in the T loop. fc phases on all quarter threads.
// ---------------------------------------------------------------------------

#define T_STEPS 128
#define DIN     4
#define HID     256
#define G4      1024
#define MROWS   32
#define NCTA    128
#define KC      64

// k-chunk packed weights [kc][j] -> float4 of W[j][4kc..4kc+3]
__device__ float4 g_whh[KC * G4];   // 1 MB
__device__ float4 g_fc1[KC * HID];  // 256 KB
__device__ float4 g_fc2[KC * HID];  // 256 KB

__global__ void pack_kernel(const float* __restrict__ W_hh,
                            const float* __restrict__ fc1_w,
                            const float* __restrict__ fc2_w) {
    int i = blockIdx.x * blockDim.x + threadIdx.x;
    if (i < KC * G4) {
        int kc = i >> 10, j = i & 1023;
        g_whh[i] = *reinterpret_cast<const float4*>(W_hh + j * HID + kc * 4);
    }
    if (i < KC * HID) {
        int kc = i >> 8, j = i & 255;
        g_fc1[i] = *reinterpret_cast<const float4*>(fc1_w + j * HID + kc * 4);
        g_fc2[i] = *reinterpret_cast<const float4*>(fc2_w + j * HID + kc * 4);
    }
}

// ---- packed f32x2 helpers --------------------------------------------------
__device__ __forceinline__ unsigned long long pk2(float lo, float hi) {
    unsigned long long r;
    asm("mov.b64 %0, {%1, %2};" : "=l"(r) : "f"(lo), "f"(hi));
    return r;
}
__device__ __forceinline__ void fma2(unsigned long long& d,
                                     unsigned long long a,
                                     unsigned long long b) {
    asm("fma.rn.f32x2 %0, %1, %2, %0;" : "+l"(d) : "l"(a), "l"(b));
}
__device__ __forceinline__ void unpk2(unsigned long long v, float& lo, float& hi) {
    asm("mov.b64 {%0, %1}, %2;" : "=f"(lo), "=f"(hi) : "l"(v));
}
__device__ __forceinline__ float sigf(float x) {
    return __fdividef(1.0f, 1.0f + __expf(-x));
}
__device__ __forceinline__ float tanhf_fast(float x) {
    float e = __expf(2.0f * x);
    return 1.0f - __fdividef(2.0f, e + 1.0f);
}
__device__ __forceinline__ void barq(int q) {
    asm volatile("bar.sync %0, %1;" :: "r"(q + 1), "r"(256) : "memory");
}

// ---- shared layout (float offsets) -----------------------------------------
#define SBUF      9216          // one [256][36] activation buffer
#define OFF_BUF   0             // 3 buffers: h ping, h pong, p2
#define OFF_C     27648         // [256][36] c state (quarter-column private)
#define OFF_PREV  36864         // [32][4]
#define OFF_WIH   36992         // [256][16]  wih[j2][g][d]
#define OFF_BG    41088         // [256][4]   gate bias per j2
#define OFF_FB1   42112         // [256]
#define OFF_FB2   42368         // [256]
#define OFF_FC3   42624         // [256][4]   fc3T[k][d]
#define OFF_B3    43648         // [4]
#define SMEM_FLOATS 43652
#define SMEM_BYTES  (SMEM_FLOATS * 4)

// fc: 1 output j2 x 8 rows (n0..n0+7) within one quarter, relu
__device__ __forceinline__ void fc_q(const float* __restrict__ src,
                                     float* __restrict__ dst,
                                     const float4* __restrict__ wbase,
                                     float bias, int j2, int n0) {
    unsigned long long acc[4];
    unsigned long long bb = pk2(bias, bias);
    acc[0] = bb; acc[1] = bb; acc[2] = bb; acc[3] = bb;
    const float4* wp = wbase + j2;
    const float* sb = src + n0;
#pragma unroll 2
    for (int kc = 0; kc < KC; kc++) {
        float4 w = wp[kc * HID];
        const float* hb = sb + kc * 144;
#pragma unroll
        for (int kk = 0; kk < 4; kk++) {
            float wk = (kk == 0) ? w.x : (kk == 1) ? w.y : (kk == 2) ? w.z : w.w;
            unsigned long long wv = pk2(wk, wk);
            ulonglong2 hA = *reinterpret_cast<const ulonglong2*>(hb + kk * 36);
            ulonglong2 hB = *reinterpret_cast<const ulonglong2*>(hb + kk * 36 + 4);
            fma2(acc[0], wv, hA.x);
            fma2(acc[1], wv, hA.y);
            fma2(acc[2], wv, hB.x);
            fma2(acc[3], wv, hB.y);
        }
    }
    float r[8];
#pragma unroll
    for (int p = 0; p < 4; p++) {
        float lo, hi; unpk2(acc[p], lo, hi);
        r[2 * p]     = fmaxf(lo, 0.0f);
        r[2 * p + 1] = fmaxf(hi, 0.0f);
    }
    float4* dp = reinterpret_cast<float4*>(dst + j2 * 36 + n0);
    dp[0] = make_float4(r[0], r[1], r[2], r[3]);
    dp[1] = make_float4(r[4], r[5], r[6], r[7]);
}

__global__ void __launch_bounds__(1024, 1)
rnn_rollout_kernel(const float* __restrict__ inputs,
                   const float* __restrict__ W_ih,
                   const float* __restrict__ b_ih,
                   const float* __restrict__ b_hh,
                   const float* __restrict__ fc1_b,
                   const float* __restrict__ fc2_b,
                   const float* __restrict__ fc3_w,
                   const float* __restrict__ fc3_b,
                   float* __restrict__ out) {
    extern __shared__ float sm[];
    float* buf    = sm + OFF_BUF;
    float* csh    = sm + OFF_C;
    float* prevsh = sm + OFF_PREV;
    float* wihsh  = sm + OFF_WIH;
    float* bgsh   = sm + OFF_BG;
    float* fb1sh  = sm + OFF_FB1;
    float* fb2sh  = sm + OFF_FB2;
    float* fc3T   = sm + OFF_FC3;
    float* b3sh   = sm + OFF_B3;

    const int tid  = threadIdx.x;
    const int j2   = tid & 255;      // unit index within quarter
    const int q    = tid >> 8;       // quarter 0..3
    const int n0   = q * 8;          // rows owned by this quarter
    const int row0 = blockIdx.x * MROWS;

    // ---- one-time init (full CTA) ----
    {
        // thread (g = q, j2) fills wih/bias for gate unit g*256+j2
        *reinterpret_cast<float4*>(wihsh + j2 * 16 + q * 4) =
            *reinterpret_cast<const float4*>(W_ih + (q * 256 + j2) * 4);
        bgsh[j2 * 4 + q] = b_ih[q * 256 + j2] + b_hh[q * 256 + j2];
    }
    if (tid < HID) { fb1sh[tid] = fc1_b[tid]; fb2sh[tid] = fc2_b[tid]; }
    if (tid < G4)  fc3T[tid] = fc3_w[(tid & 3) * HID + (tid >> 2)];
    if (tid < DIN) b3sh[tid] = fc3_b[tid];
    for (int i = tid; i < SBUF; i += 1024) buf[i] = 0.0f;      // h0 = 0
    for (int i = tid; i < SBUF; i += 1024) csh[i] = 0.0f;      // c0 = 0
    if (tid < MROWS * DIN)
        prevsh[tid] = inputs[((size_t)(row0 + (tid >> 2)) * T_STEPS) * DIN + (tid & 3)];
    __syncthreads();   // the ONLY full-CTA barrier

    for (int t = 0; t < T_STEPS; t++) {
        const int par = t & 1;
        float* hin  = buf + par * SBUF;
        float* hout = buf + (par ^ 1) * SBUF;
        float* p1   = hin;                 // fc1 overwrites dead h_in
        float* p2   = buf + 2 * SBUF;

        // ---- phase A: gate GEMM + fused LSTM elementwise ----
        unsigned long long acc[4][4];
        {
            float4 wg0 = *reinterpret_cast<const float4*>(wihsh + j2 * 16);
            float4 wg1 = *reinterpret_cast<const float4*>(wihsh + j2 * 16 + 4);
            float4 wg2 = *reinterpret_cast<const float4*>(wihsh + j2 * 16 + 8);
            float4 wg3 = *reinterpret_cast<const float4*>(wihsh + j2 * 16 + 12);
            float4 bg  = *reinterpret_cast<const float4*>(bgsh + j2 * 4);
#pragma unroll
            for (int p = 0; p < 4; p++) {
                float4 pa = *reinterpret_cast<const float4*>(prevsh + 4 * (n0 + 2 * p));
                float4 pb = *reinterpret_cast<const float4*>(prevsh + 4 * (n0 + 2 * p + 1));
                acc[0][p] = pk2(bg.x + wg0.x*pa.x + wg0.y*pa.y + wg0.z*pa.z + wg0.w*pa.w,
                                bg.x + wg0.x*pb.x + wg0.y*pb.y + wg0.z*pb.z + wg0.w*pb.w);
                acc[1][p] = pk2(bg.y + wg1.x*pa.x + wg1.y*pa.y + wg1.z*pa.z + wg1.w*pa.w,
                                bg.y + wg1.x*pb.x + wg1.y*pb.y + wg1.z*pb.z + wg1.w*pb.w);
                acc[2][p] = pk2(bg.z + wg2.x*pa.x + wg2.y*pa.y + wg2.z*pa.z + wg2.w*pa.w,
                                bg.z + wg2.x*pb.x + wg2.y*pb.y + wg2.z*pb.z + wg2.w*pb.w);
                acc[3][p] = pk2(bg.w + wg3.x*pa.x + wg3.y*pa.y + wg3.z*pa.z + wg3.w*pa.w,
                                bg.w + wg3.x*pb.x + wg3.y*pb.y + wg3.z*pb.z + wg3.w*pb.w);
            }
        }
        {
            const float4* gw = g_whh + j2;
            const float* hq = hin + n0;
#pragma unroll 1
            for (int kc = 0; kc < KC; kc++) {
                float wa[4][4];
                *(float4*)wa[0] = gw[kc * G4];
                *(float4*)wa[1] = gw[kc * G4 + 256];
                *(float4*)wa[2] = gw[kc * G4 + 512];
                *(float4*)wa[3] = gw[kc * G4 + 768];
                const float* hb = hq + kc * 144;
#pragma unroll
                for (int kk = 0; kk < 4; kk++) {
                    ulonglong2 hA = *reinterpret_cast<const ulonglong2*>(hb + kk * 36);
                    ulonglong2 hB = *reinterpret_cast<const ulonglong2*>(hb + kk * 36 + 4);
#pragma unroll
                    for (int g = 0; g < 4; g++) {
                        unsigned long long w = pk2(wa[g][kk], wa[g][kk]);
                        fma2(acc[g][0], w, hA.x);
                        fma2(acc[g][1], w, hA.y);
                        fma2(acc[g][2], w, hB.x);
                        fma2(acc[g][3], w, hB.y);
                    }
                }
            }
        }
        // fused LSTM elementwise: c in quarter-private smem column
        {
            float hv[8];
#pragma unroll
            for (int p = 0; p < 4; p++) {
                float gi0, gi1, gf0, gf1, gg0, gg1, go0, go1;
                unpk2(acc[0][p], gi0, gi1);
                unpk2(acc[1][p], gf0, gf1);
                unpk2(acc[2][p], gg0, gg1);
                unpk2(acc[3][p], go0, go1);
                const int n = n0 + 2 * p;
                float c0 = sigf(gf0) * csh[j2 * 36 + n]     + sigf(gi0) * tanhf_fast(gg0);
                float c1 = sigf(gf1) * csh[j2 * 36 + n + 1] + sigf(gi1) * tanhf_fast(gg1);
                csh[j2 * 36 + n]     = c0;
                csh[j2 * 36 + n + 1] = c1;
                hv[2 * p]     = sigf(go0) * tanhf_fast(c0);
                hv[2 * p + 1] = sigf(go1) * tanhf_fast(c1);
            }
            float4* hp = reinterpret_cast<float4*>(hout + j2 * 36 + n0);
            hp[0] = make_float4(hv[0], hv[1], hv[2], hv[3]);
            hp[1] = make_float4(hv[4], hv[5], hv[6], hv[7]);
        }
        barq(q);

        // ---- phase C: fc1 (hout -> p1) ----
        fc_q(hout, p1, g_fc1, fb1sh[j2], j2, n0);
        barq(q);

        // ---- phase D: fc2 (p1 -> p2) ----
        fc_q(p1, p2, g_fc2, fb2sh[j2], j2, n0);
        barq(q);

        // ---- phase E: fc3 + residual. 256 thr = 8 rows x 4 d x 8 k-slices
        {
            const int out_id = j2 >> 3;        // 0..31
            const int s      = j2 & 7;         // k-slice
            const int rowc   = n0 + (out_id >> 2);
            const int d      = out_id & 3;
            const float* pp  = p2 + rowc;
            const float* f3  = fc3T + d;
            float a = 0.0f;
#pragma unroll 8
            for (int i = 0; i < 32; i++) {
                int k = s * 32 + i;
                a = fmaf(pp[k * 36], f3[k * 4], a);
            }
            a += __shfl_xor_sync(0xffffffffu, a, 1);
            a += __shfl_xor_sync(0xffffffffu, a, 2);
            a += __shfl_xor_sync(0xffffffffu, a, 4);
            if (s == 0) {
                float r = a + b3sh[d] + prevsh[rowc * 4 + d];
                out[((size_t)(row0 + rowc) * T_STEPS + t) * DIN + d] = r;
                prevsh[rowc * 4 + d] = r;
            }
        }
        barq(q);
    }
}

extern "C" void kernel_launch(void* const* d_in, const int* in_sizes, int n_in,
                              void* d_out, int out_size) {
    const float* inputs = (const float*)d_in[0];
    const float* W_ih   = (const float*)d_in[1];
    const float* W_hh   = (const float*)d_in[2];
    const float* b_ih   = (const float*)d_in[3];
    const float* b_hh   = (const float*)d_in[4];
    const float* fc1_w  = (const float*)d_in[5];
    const float* fc1_b  = (const float*)d_in[6];
    const float* fc2_w  = (const float*)d_in[7];
    const float* fc2_b  = (const float*)d_in[8];
    const float* fc3_w  = (const float*)d_in[9];
    const float* fc3_b  = (const float*)d_in[10];
    float* out = (float*)d_out;

    pack_kernel<<<64, 1024>>>(W_hh, fc1_w, fc2_w);

    cudaFuncSetAttribute(rnn_rollout_kernel,
                         cudaFuncAttributeMaxDynamicSharedMemorySize, SMEM_BYTES);
    rnn_rollout_kernel<<<NCTA, 1024, SMEM_BYTES>>>(
        inputs, W_ih, b_ih, b_hh, fc1_b, fc2_b, fc3_w, fc3_b, out);
}

// round 5
// speedup vs baseline: 1.1688x; 1.0423x over previous
#include <cuda_runtime.h>

// ---------------------------------------------------------------------------
// GraphRNNDecoder rollout. N=4096 rows, T=128 steps, D=4, H=256.
// 128 persistent CTAs x 1024 threads, 32 rows per CTA.
// R5: warp covers ALL 32 rows. Lane (rg in [0,8), u in [0,4)) handles
// 8 gate-units (2 j2 x 4 gates) x 4 rows. Weight LDG.128 = 64B unique x8 dup
// -> 1 wavefront (vs 4); h LDS = 128B unique -> L1 wavefronts halved.
// ---------------------------------------------------------------------------

#define T_STEPS 128
#define DIN     4
#define HID     256
#define G4      1024
#define MROWS   32
#define NCTA    128
#define KC      64

// k-chunk packed weights [kc][unit] -> float4 of W[unit][4kc..4kc+3]
__device__ float4 g_whh[KC * G4];   // 1 MB
__device__ float4 g_fc1[KC * HID];  // 256 KB
__device__ float4 g_fc2[KC * HID];  // 256 KB

__global__ void pack_kernel(const float* __restrict__ W_hh,
                            const float* __restrict__ fc1_w,
                            const float* __restrict__ fc2_w) {
    int i = blockIdx.x * blockDim.x + threadIdx.x;
    if (i < KC * G4) {
        int kc = i >> 10, j = i & 1023;
        g_whh[i] = *reinterpret_cast<const float4*>(W_hh + j * HID + kc * 4);
    }
    if (i < KC * HID) {
        int kc = i >> 8, j = i & 255;
        g_fc1[i] = *reinterpret_cast<const float4*>(fc1_w + j * HID + kc * 4);
        g_fc2[i] = *reinterpret_cast<const float4*>(fc2_w + j * HID + kc * 4);
    }
}

// ---- packed f32x2 helpers --------------------------------------------------
__device__ __forceinline__ unsigned long long pk2(float lo, float hi) {
    unsigned long long r;
    asm("mov.b64 %0, {%1, %2};" : "=l"(r) : "f"(lo), "f"(hi));
    return r;
}
__device__ __forceinline__ void fma2(unsigned long long& d,
                                     unsigned long long a,
                                     unsigned long long b) {
    asm("fma.rn.f32x2 %0, %1, %2, %0;" : "+l"(d) : "l"(a), "l"(b));
}
__device__ __forceinline__ void unpk2(unsigned long long v, float& lo, float& hi) {
    asm("mov.b64 {%0, %1}, %2;" : "=f"(lo), "=f"(hi) : "l"(v));
}
__device__ __forceinline__ float sigf(float x) {
    return __fdividef(1.0f, 1.0f + __expf(-x));
}
__device__ __forceinline__ float tanhf_fast(float x) {
    float e = __expf(2.0f * x);
    return 1.0f - __fdividef(2.0f, e + 1.0f);
}

// ---- shared layout (float offsets) -----------------------------------------
#define SBUF      9216          // one [256][36] activation buffer
#define OFF_BUF   0             // 3 buffers: h ping, h pong, p2
#define OFF_C     27648         // [256][36] c state
#define OFF_PREV  36864         // [32][4]
#define OFF_WIH   36992         // [1024][4]
#define OFF_BG    41088         // [1024]
#define OFF_FB1   42112         // [256]
#define OFF_FB2   42368         // [256]
#define OFF_FC3   42624         // [256][4]  fc3T[k][d]
#define OFF_B3    43648         // [4]
#define SMEM_FLOATS 43652
#define SMEM_BYTES  (SMEM_FLOATS * 4)

// fc: 2 units (jb, jb+4) x 4 rows (r0..r0+3), relu, dst [unit][36]
__device__ __forceinline__ void fc_phase(const float* __restrict__ src,
                                         float* __restrict__ dst,
                                         const float4* __restrict__ wbase,
                                         const float* __restrict__ bsh,
                                         int jb, int r0) {
    unsigned long long acc[4];
    {
        float b0 = bsh[jb], b1 = bsh[jb + 4];
        acc[0] = acc[1] = pk2(b0, b0);
        acc[2] = acc[3] = pk2(b1, b1);
    }
    const float* hq = src + r0;
    const float4* gw = wbase + jb;
#pragma unroll 2
    for (int kc = 0; kc < KC; kc++) {
        const float* hb = hq + kc * 144;
        ulonglong2 h0 = *reinterpret_cast<const ulonglong2*>(hb);
        ulonglong2 h1 = *reinterpret_cast<const ulonglong2*>(hb + 36);
        ulonglong2 h2 = *reinterpret_cast<const ulonglong2*>(hb + 72);
        ulonglong2 h3 = *reinterpret_cast<const ulonglong2*>(hb + 108);
        const float4* wk = gw + kc * HID;
#pragma unroll
        for (int half = 0; half < 2; half++) {
            float4 wv = wk[half * 4];
            const int a = half * 2;
            unsigned long long w2;
            w2 = pk2(wv.x, wv.x); fma2(acc[a], w2, h0.x); fma2(acc[a + 1], w2, h0.y);
            w2 = pk2(wv.y, wv.y); fma2(acc[a], w2, h1.x); fma2(acc[a + 1], w2, h1.y);
            w2 = pk2(wv.z, wv.z); fma2(acc[a], w2, h2.x); fma2(acc[a + 1], w2, h2.y);
            w2 = pk2(wv.w, wv.w); fma2(acc[a], w2, h3.x); fma2(acc[a + 1], w2, h3.y);
        }
    }
#pragma unroll
    for (int half = 0; half < 2; half++) {
        const int j = jb + half * 4;
        float v0, v1, v2, v3;
        unpk2(acc[half * 2], v0, v1);
        unpk2(acc[half * 2 + 1], v2, v3);
        *reinterpret_cast<float4*>(dst + j * 36 + r0) =
            make_float4(fmaxf(v0, 0.f), fmaxf(v1, 0.f), fmaxf(v2, 0.f), fmaxf(v3, 0.f));
    }
}

__global__ void __launch_bounds__(1024, 1)
rnn_rollout_kernel(const float* __restrict__ inputs,
                   const float* __restrict__ W_ih,
                   const float* __restrict__ b_ih,
                   const float* __restrict__ b_hh,
                   const float* __restrict__ fc1_b,
                   const float* __restrict__ fc2_b,
                   const float* __restrict__ fc3_w,
                   const float* __restrict__ fc3_b,
                   float* __restrict__ out) {
    extern __shared__ float sm[];
    float* buf    = sm + OFF_BUF;
    float* csh    = sm + OFF_C;
    float* prevsh = sm + OFF_PREV;
    float* wihsh  = sm + OFF_WIH;
    float* bgsh   = sm + OFF_BG;
    float* fb1sh  = sm + OFF_FB1;
    float* fb2sh  = sm + OFF_FB2;
    float* fc3T   = sm + OFF_FC3;
    float* b3sh   = sm + OFF_B3;

    const int tid  = threadIdx.x;
    const int w    = tid >> 5;       // warp 0..31
    const int l    = tid & 31;
    const int u    = l & 3;          // unit lane
    const int rg   = l >> 2;         // rowgroup 0..7
    const int r0   = rg * 4;         // 4 rows per thread
    const int jb   = w * 8 + u;      // thread's j2 pair: jb, jb+4
    const int row0 = blockIdx.x * MROWS;

    // ---- one-time init ----
    *reinterpret_cast<float4*>(wihsh + tid * 4) =
        *reinterpret_cast<const float4*>(W_ih + tid * 4);
    bgsh[tid] = b_ih[tid] + b_hh[tid];
    if (tid < HID) { fb1sh[tid] = fc1_b[tid]; fb2sh[tid] = fc2_b[tid]; }
    fc3T[tid] = fc3_w[(tid & 3) * HID + (tid >> 2)];
    if (tid < DIN) b3sh[tid] = fc3_b[tid];
    for (int i = tid; i < 3 * SBUF; i += 1024) buf[i] = 0.0f;
    for (int i = tid; i < SBUF; i += 1024) csh[i] = 0.0f;
    if (tid < MROWS * DIN)
        prevsh[tid] = inputs[((size_t)(row0 + (tid >> 2)) * T_STEPS) * DIN + (tid & 3)];
    __syncthreads();

    for (int t = 0; t < T_STEPS; t++) {
        const int par = t & 1;
        float* hin  = buf + par * SBUF;
        float* hout = buf + (par ^ 1) * SBUF;
        float* p1   = hin;                 // fc1 overwrites dead h_in
        float* p2   = buf + 2 * SBUF;

        // ---- phase A: gate GEMM (8 units x 4 rows per thread) ----
        unsigned long long acc[16];
        {
            float4 pv0 = *reinterpret_cast<const float4*>(prevsh + r0 * 4);
            float4 pv1 = *reinterpret_cast<const float4*>(prevsh + (r0 + 1) * 4);
            float4 pv2 = *reinterpret_cast<const float4*>(prevsh + (r0 + 2) * 4);
            float4 pv3 = *reinterpret_cast<const float4*>(prevsh + (r0 + 3) * 4);
#pragma unroll
            for (int half = 0; half < 2; half++) {
                const int j2 = jb + half * 4;
#pragma unroll
                for (int g = 0; g < 4; g++) {
                    const int unit = g * 256 + j2;
                    float4 wg = *reinterpret_cast<const float4*>(wihsh + unit * 4);
                    float b = bgsh[unit];
                    float s0 = b + wg.x*pv0.x + wg.y*pv0.y + wg.z*pv0.z + wg.w*pv0.w;
                    float s1 = b + wg.x*pv1.x + wg.y*pv1.y + wg.z*pv1.z + wg.w*pv1.w;
                    float s2 = b + wg.x*pv2.x + wg.y*pv2.y + wg.z*pv2.z + wg.w*pv2.w;
                    float s3 = b + wg.x*pv3.x + wg.y*pv3.y + wg.z*pv3.z + wg.w*pv3.w;
                    acc[(half * 4 + g) * 2]     = pk2(s0, s1);
                    acc[(half * 4 + g) * 2 + 1] = pk2(s2, s3);
                }
            }
        }
        {
            const float* hq = hin + r0;
            const float4* gw = g_whh + jb;
#pragma unroll 1
            for (int kc = 0; kc < KC; kc++) {
                const float* hb = hq + kc * 144;
                ulonglong2 h0 = *reinterpret_cast<const ulonglong2*>(hb);
                ulonglong2 h1 = *reinterpret_cast<const ulonglong2*>(hb + 36);
                ulonglong2 h2 = *reinterpret_cast<const ulonglong2*>(hb + 72);
                ulonglong2 h3 = *reinterpret_cast<const ulonglong2*>(hb + 108);
                const float4* wk = gw + kc * G4;
#pragma unroll
                for (int half = 0; half < 2; half++) {
#pragma unroll
                    for (int g = 0; g < 4; g++) {
                        float4 wv = wk[g * 256 + half * 4];
                        const int a = (half * 4 + g) * 2;
                        unsigned long long w2;
                        w2 = pk2(wv.x, wv.x); fma2(acc[a], w2, h0.x); fma2(acc[a+1], w2, h0.y);
                        w2 = pk2(wv.y, wv.y); fma2(acc[a], w2, h1.x); fma2(acc[a+1], w2, h1.y);
                        w2 = pk2(wv.z, wv.z); fma2(acc[a], w2, h2.x); fma2(acc[a+1], w2, h2.y);
                        w2 = pk2(wv.w, wv.w); fma2(acc[a], w2, h3.x); fma2(acc[a+1], w2, h3.y);
                    }
                }
            }
        }
        // ---- fused LSTM elementwise: 2 j2 x 4 rows per thread ----
#pragma unroll
        for (int half = 0; half < 2; half++) {
            const int j2 = jb + half * 4;
            const int a  = half * 8;
            float4 cv = *reinterpret_cast<const float4*>(csh + j2 * 36 + r0);
            float i0,i1,i2,i3, f0,f1,f2,f3, g0,g1,g2,g3, o0,o1,o2,o3;
            unpk2(acc[a + 0], i0, i1); unpk2(acc[a + 1], i2, i3);
            unpk2(acc[a + 2], f0, f1); unpk2(acc[a + 3], f2, f3);
            unpk2(acc[a + 4], g0, g1); unpk2(acc[a + 5], g2, g3);
            unpk2(acc[a + 6], o0, o1); unpk2(acc[a + 7], o2, o3);
            float c0 = sigf(f0) * cv.x + sigf(i0) * tanhf_fast(g0);
            float c1 = sigf(f1) * cv.y + sigf(i1) * tanhf_fast(g1);
            float c2 = sigf(f2) * cv.z + sigf(i2) * tanhf_fast(g2);
            float c3 = sigf(f3) * cv.w + sigf(i3) * tanhf_fast(g3);
            *reinterpret_cast<float4*>(csh + j2 * 36 + r0) = make_float4(c0, c1, c2, c3);
            *reinterpret_cast<float4*>(hout + j2 * 36 + r0) =
                make_float4(sigf(o0) * tanhf_fast(c0), sigf(o1) * tanhf_fast(c1),
                            sigf(o2) * tanhf_fast(c2), sigf(o3) * tanhf_fast(c3));
        }
        __syncthreads();

        // ---- fc1: hout -> p1 ----
        fc_phase(hout, p1, g_fc1, fb1sh, jb, r0);
        __syncthreads();

        // ---- fc2: p1 -> p2 ----
        fc_phase(p1, p2, g_fc2, fb2sh, jb, r0);
        __syncthreads();

        // ---- fc3 + residual: warp w = row w; lane = (s in [0,8)) * 4 + d ----
        {
            const int row = w;
            const int d   = l & 3;
            const int s   = l >> 2;
            const float* pp = p2 + row;
            float a0 = 0.f;
#pragma unroll 8
            for (int i = 0; i < 32; i++) {
                const int k = i * 8 + s;
                a0 = fmaf(pp[k * 36], fc3T[k * 4 + d], a0);
            }
            a0 += __shfl_xor_sync(0xffffffffu, a0, 4);
            a0 += __shfl_xor_sync(0xffffffffu, a0, 8);
            a0 += __shfl_xor_sync(0xffffffffu, a0, 16);
            if (s == 0) {
                float r = a0 + b3sh[d] + prevsh[row * 4 + d];
                out[((size_t)(row0 + row) * T_STEPS + t) * DIN + d] = r;
                prevsh[row * 4 + d] = r;
            }
        }
        __syncthreads();
    }
}

extern "C" void kernel_launch(void* const* d_in, const int* in_sizes, int n_in,
                              void* d_out, int out_size) {
    const float* inputs = (const float*)d_in[0];
    const float* W_ih   = (const float*)d_in[1];
    const float* W_hh   = (const float*)d_in[2];
    const float* b_ih   = (const float*)d_in[3];
    const float* b_hh   = (const float*)d_in[4];
    const float* fc1_w  = (const float*)d_in[5];
    const float* fc1_b  = (const float*)d_in[6];
    const float* fc2_w  = (const float*)d_in[7];
    const float* fc2_b  = (const float*)d_in[8];
    const float* fc3_w  = (const float*)d_in[9];
    const float* fc3_b  = (const float*)d_in[10];
    float* out = (float*)d_out;

    pack_kernel<<<64, 1024>>>(W_hh, fc1_w, fc2_w);

    cudaFuncSetAttribute(rnn_rollout_kernel,
                         cudaFuncAttributeMaxDynamicSharedMemorySize, SMEM_BYTES);
    rnn_rollout_kernel<<<NCTA, 1024, SMEM_BYTES>>>(
        inputs, W_ih, b_ih, b_hh, fc1_b, fc2_b, fc3_w, fc3_b, out);
}